// round 6
// baseline (speedup 1.0000x reference)
#include <cuda_runtime.h>
#include <cstdint>
#include <math.h>

#define NT    1024
#define NPIX  (8*4*1024*1024)
#define NWC   2048        // window LUT cells (4096-wide in d), covers k in [81,144]
#define WLO   80
#define WNB   64

// ---- static device scratch ----
__device__ int  g_B[NT];            // integer boundaries: M > B[k] <=> fp32(M*c) > T[k]
__device__ int2 g_wlut[NWC];        // {kb, B[kb]} per 4096-wide d-cell, window only
__device__ int  g_cnt80;            // count(u <= 80) == count(M > B[80])
__device__ int  g_fine[WNB];        // count(u == 81+j)
__device__ int  g_hist256[256];     // fallback histogram
__device__ int  g_flag, g_a;
__device__ unsigned g_bin[NPIX/4];  // 4x u8: 0 (u<=80) | exact u in [81,144] | 255 (u>=145)

__device__ __forceinline__ double wscale() {
  const float W = (float)(1.0 / 25.0);
  return (double)W / 8388608.0;
}

// ---------------------------------------------------------------------------
// K0: ladder -> exact integer boundaries -> window LUT; zero counters.
// ---------------------------------------------------------------------------
__global__ void __launch_bounds__(1024) k_setup() {
  __shared__ float Tsh[NT];
  __shared__ int  Bsh[NT];
  const int t = threadIdx.x;
  if (t == 0) {
    float v = 0.5f;
    for (int k = 0; k < NT; ++k) { Tsh[k] = v; v = v - 0.0005f; }
    g_cnt80 = 0; g_flag = 0;
  }
  if (t < WNB) g_fine[t] = 0;
  if (t < 256) g_hist256[t] = 0;
  __syncthreads();
  {
    const double c = wscale();
    float T = Tsh[t];
    double dM = (double)T / c;
    long long Mg = (long long)floor(dM);
    if (Mg < -1) Mg = -1;
    if (Mg > 400000000LL) Mg = 400000000LL;
    while ((float)((double)(Mg + 1) * c) <= T) Mg++;
    while (Mg >= 0 && (float)((double)Mg * c) > T) Mg--;
    Bsh[t] = (int)Mg;
    g_B[t] = (int)Mg;
  }
  __syncthreads();
  const int B0 = Bsh[0];
  const int d80 = B0 - Bsh[WLO];
#pragma unroll
  for (int q = 0; q < NWC / 1024; ++q) {
    const int i = q * 1024 + t;
    const int Mh = B0 - (d80 + (i << 12));   // largest M in cell
    int lo = 1, hi = 1023, res = 1023;       // smallest k with Mh > B[k]
    while (lo <= hi) {
      int mid = (lo + hi) >> 1;
      if (Mh > Bsh[mid]) { res = mid; hi = mid - 1; }
      else lo = mid + 1;
    }
    g_wlut[i] = make_int2(res, Bsh[res]);
  }
}

// ---------------------------------------------------------------------------
// K1: exact integer 5x5 box blur + classify: 2 register compares for 87% of
//     pixels, single-LDS int2 window LUT for the rest. Fused fine histogram.
//     8 warps = 8 x 128-col strips; 32-row band; grid 1024. Pipelined loads.
// ---------------------------------------------------------------------------
__global__ void __launch_bounds__(256) k_blur(const float* __restrict__ x) {
  __shared__ int2 wl[NWC];               // 16KB window LUT
  __shared__ int fh[8][WNB];             // per-warp fine histograms
  const int tid = threadIdx.x, lane = tid & 31, w = tid >> 5;
  {
    const uint4* src = (const uint4*)g_wlut;
    uint4* dst = (uint4*)wl;
    for (int i = tid; i < NWC / 2; i += 256) dst[i] = src[i];
  }
  if (lane < 32) { fh[w][lane] = 0; fh[w][lane + 32] = 0; }
  const int B0 = g_B[0], B80 = g_B[WLO], B144 = g_B[WLO + WNB];
  const int d80 = B0 - B80;
  __syncthreads();

  const int ch = blockIdx.x >> 5;
  const int y0 = (blockIdx.x & 31) << 5;
  const float4* xo = (const float4*)x + ((size_t)ch << 18);
  const float*  xs = x + ((size_t)ch << 20);
  unsigned* bp = g_bin + ((size_t)ch << 18);

  const int c0 = (w << 7) + (lane << 2);
  const int hcol = (lane == 0) ? (c0 - 2) : (c0 + 4);
  const bool hval = (lane == 0) ? (w > 0) : ((lane == 31) && (w < 7));
  int cnt80 = 0;

  auto ldOwn = [&](int y) -> int4 {
    int4 m = make_int4(0, 0, 0, 0);
    if ((unsigned)y < 1024u) {
      float4 v = __ldg(xo + ((size_t)y << 8) + tid);
      m.x = (int)(v.x * 8388608.0f);
      m.y = (int)(v.y * 8388608.0f);
      m.z = (int)(v.z * 8388608.0f);
      m.w = (int)(v.w * 8388608.0f);
    }
    return m;
  };
  auto ldHalo = [&](int y) -> int2 {
    int2 m = make_int2(0, 0);
    if (hval && (unsigned)y < 1024u) {
      float2 v = __ldg((const float2*)(xs + ((size_t)y << 10) + hcol));
      m.x = (int)(v.x * 8388608.0f);
      m.y = (int)(v.y * 8388608.0f);
    }
    return m;
  };
  // classify: 0 if u<=80 (count), 255 if u>=145, else exact u via window LUT
  auto classify = [&](int M) -> unsigned {
    if (M > B80) { cnt80++; return 0u; }
    if (M <= B144) return 255u;
    unsigned idx = (unsigned)((B0 - M) - d80) >> 12;
    if (idx > NWC - 1) idx = NWC - 1;
    const int2 e = wl[idx];
    const int u = e.x + (M <= e.y);
    atomicAdd(&fh[w][u - (WLO + 1)], 1);
    return (unsigned)u;
  };

  int4 r0 = ldOwn(y0 - 2), r1 = ldOwn(y0 - 1), r2 = ldOwn(y0), r3 = ldOwn(y0 + 1);
  int2 h0 = ldHalo(y0 - 2), h1 = ldHalo(y0 - 1), h2 = ldHalo(y0), h3 = ldHalo(y0 + 1);
  int4 pn = ldOwn(y0 + 2);
  int2 ph = ldHalo(y0 + 2);
  int4 S;
  S.x = r0.x + r1.x + r2.x + r3.x;
  S.y = r0.y + r1.y + r2.y + r3.y;
  S.z = r0.z + r1.z + r2.z + r3.z;
  S.w = r0.w + r1.w + r2.w + r3.w;
  int2 Sh = make_int2(h0.x + h1.x + h2.x + h3.x, h0.y + h1.y + h2.y + h3.y);

#pragma unroll 2
  for (int yy = 0; yy < 32; ++yy) {
    const int y = y0 + yy;
    const int4 nw = pn;
    const int2 nh = ph;
    pn = ldOwn(y + 3);                  // prefetch one row ahead
    ph = ldHalo(y + 3);
    S.x += nw.x; S.y += nw.y; S.z += nw.z; S.w += nw.w;
    Sh.x += nh.x; Sh.y += nh.y;

    int l2 = __shfl_up_sync(0xFFFFFFFFu, S.z, 1);
    int l1 = __shfl_up_sync(0xFFFFFFFFu, S.w, 1);
    int q1 = __shfl_down_sync(0xFFFFFFFFu, S.x, 1);
    int q2 = __shfl_down_sync(0xFFFFFFFFu, S.y, 1);
    if (lane == 0)  { l2 = Sh.x; l1 = Sh.y; }
    if (lane == 31) { q1 = Sh.x; q2 = Sh.y; }

    const int Mx = l2 + l1 + S.x + S.y + S.z;
    const int My = Mx - l2 + S.w;
    const int Mz = My - l1 + q1;
    const int Mw = Mz - S.x + q2;

    const unsigned u0 = classify(Mx), u1 = classify(My);
    const unsigned u2 = classify(Mz), u3 = classify(Mw);
    bp[((size_t)y << 8) + tid] = u0 | (u1 << 8) | (u2 << 16) | (u3 << 24);

    S.x -= r0.x; S.y -= r0.y; S.z -= r0.z; S.w -= r0.w;
    Sh.x -= h0.x; Sh.y -= h0.y;
    r0 = r1; r1 = r2; r2 = r3; r3 = nw;
    h0 = h1; h1 = h2; h2 = h3; h3 = nh;
  }

  cnt80 += __shfl_down_sync(0xFFFFFFFFu, cnt80, 16);
  cnt80 += __shfl_down_sync(0xFFFFFFFFu, cnt80, 8);
  cnt80 += __shfl_down_sync(0xFFFFFFFFu, cnt80, 4);
  cnt80 += __shfl_down_sync(0xFFFFFFFFu, cnt80, 2);
  cnt80 += __shfl_down_sync(0xFFFFFFFFu, cnt80, 1);
  if (lane == 0) atomicAdd(&g_cnt80, cnt80);

  __syncthreads();
  if (tid < WNB) {
    int s = fh[0][tid] + fh[1][tid] + fh[2][tid] + fh[3][tid]
          + fh[4][tid] + fh[5][tid] + fh[6][tid] + fh[7][tid];
    if (s) atomicAdd(&g_fine[tid], s);
  }
}

// ---------------------------------------------------------------------------
// K2: exact replay of both while-loops on counts; sets g_a or g_flag.
// ---------------------------------------------------------------------------
__global__ void __launch_bounds__(64) k_flag() {
  __shared__ int sf[WNB];
  const int t = threadIdx.x;
  sf[t] = g_fine[t];
  __syncthreads();
  if (t != 0) return;
  const float invN = 1.0f / 33554432.0f;   // N = 2^25
  int flag = 0, a = 0;
  int C = g_cnt80;                         // cum count at k = 80
  if ((float)C * invN >= 0.84f) flag = 1;
  else {
    int ks = -1;
    for (int j = 0; j < WNB; ++j) {
      C += sf[j];
      if ((float)C * invN >= 0.84f) { ks = WLO + 1 + j; break; }
    }
    if (ks < 0) flag = 1;
    else {
      int k = ks;
      while ((float)C * invN > 0.86f) {    // statistically never iterates
        if (k == WLO) { flag = 1; break; }
        C -= sf[k - (WLO + 1)];
        k--;
      }
      a = k;
    }
  }
  g_flag = flag;
  if (!flag) g_a = a;
}

// ---------------------------------------------------------------------------
// K3: fallback (never taken): recompute exact u for every pixel + histogram.
// ---------------------------------------------------------------------------
__global__ void __launch_bounds__(256) k_fallback(const float* __restrict__ x) {
  if (!g_flag) return;
  __shared__ int Bsh[256];
  __shared__ int h[256];
  const int tid = threadIdx.x;
  if (tid < 256) { Bsh[tid] = g_B[tid]; h[tid] = 0; }
  __syncthreads();
  const int ch = blockIdx.x >> 5;
  const int y0 = (blockIdx.x & 31) << 5;
  const float* xp = x + ((size_t)ch << 20);
  unsigned char* bb = (unsigned char*)g_bin + ((size_t)ch << 20);
  for (int i = tid; i < 32 * 1024; i += 256) {
    const int yy = i >> 10, c = i & 1023;
    const int y = y0 + yy;
    int M = 0;
    for (int dy = -2; dy <= 2; ++dy)
      for (int dx = -2; dx <= 2; ++dx) {
        const int yv = y + dy, cv = c + dx;
        if ((unsigned)yv < 1024u && (unsigned)cv < 1024u)
          M += (int)(xp[((size_t)yv << 10) + cv] * 8388608.0f);
      }
    // smallest k in [0,255] with M > B[k], else 255
    int lo = 0, hi = 255, res = 255;
    while (lo <= hi) {
      int mid = (lo + hi) >> 1;
      if (M > Bsh[mid]) { res = mid; hi = mid - 1; }
      else lo = mid + 1;
    }
    bb[((size_t)y << 10) + c] = (unsigned char)res;
    atomicAdd(&h[res], 1);
  }
  __syncthreads();
  if (h[tid]) atomicAdd(&g_hist256[tid], h[tid]);
}

// ---------------------------------------------------------------------------
// K4: threshold + bitwise morphological close + expand. 1024x32 tiles.
// ---------------------------------------------------------------------------
__global__ void __launch_bounds__(256) k_morph(float* __restrict__ out) {
  __shared__ unsigned bits[40][33];
  __shared__ unsigned hd[40][33];
  __shared__ unsigned dv[36][33];
  __shared__ unsigned he[36][33];
  __shared__ int a_s;
  const int tid  = threadIdx.x;
  const int lane = tid & 31;
  const int wid  = tid >> 5;
  const int ch = blockIdx.x >> 5;
  const int y0 = (blockIdx.x & 31) << 5;
  const unsigned* bw = g_bin + ((size_t)ch << 18);

  if (tid == 0) {
    if (!g_flag) a_s = g_a;
    else {                                  // fallback pick (never runs)
      const float invN = 1.0f / 33554432.0f;
      int C = 0, k = 254;
      for (int j = 0; j <= 254; ++j) {
        C += g_hist256[j];
        if ((float)C * invN >= 0.84f) { k = j; break; }
      }
      while (k > 0 && (float)C * invN > 0.86f) { C -= g_hist256[k]; k--; }
      a_s = k;
    }
  }
  __syncthreads();
  const int a = a_s;
  // SWAR constants for per-byte (u <= a)
  const unsigned C7 = (unsigned)(127 - (a & 127)) * 0x01010101u;
  const bool alow = a < 128;

  // phase 1: threshold bitmasks (SWAR byte-compare + nibble compress)
  for (int r = wid; r < 40; r += 8) {
    const int gy = y0 - 4 + r;
    const bool in = (unsigned)gy < 1024u;
    for (int seg = 0; seg < 8; ++seg) {
      unsigned v = 0;
      if (in) {
        const unsigned pk = __ldg(&bw[((size_t)gy << 8) + (seg << 5) + lane]);
        const unsigned hi = pk & 0x80808080u;
        const unsigned m  = ((pk & 0x7F7F7F7Fu) + C7) & 0x80808080u;
        const unsigned gt = alow ? (hi | m) : (hi & m);   // msb per byte: u > a
        const unsigned vb = ((~gt) >> 7) & 0x01010101u;   // 1 per byte: u <= a
        const unsigned nib = (vb * 0x01020408u) >> 24;
        v = nib << ((lane & 7) << 2);
        v |= __shfl_xor_sync(0xFFFFFFFFu, v, 1);
        v |= __shfl_xor_sync(0xFFFFFFFFu, v, 2);
        v |= __shfl_xor_sync(0xFFFFFFFFu, v, 4);
      }
      if ((lane & 7) == 0) bits[r][(seg << 2) + (lane >> 3)] = v;
    }
  }
  __syncthreads();

  // phase 2: horizontal dilate (0-fill)
  for (int idx = tid; idx < 40 * 32; idx += 256) {
    const int r = idx >> 5, w = idx & 31;
    const unsigned u = bits[r][w];
    const unsigned L = w ? bits[r][w - 1] : 0u;
    const unsigned R = (w < 31) ? bits[r][w + 1] : 0u;
    hd[r][w] = u | __funnelshift_r(u, R, 1) | __funnelshift_r(u, R, 2)
                 | __funnelshift_l(L, u, 1) | __funnelshift_l(L, u, 2);
  }
  __syncthreads();

  // phase 3: vertical dilate
  for (int idx = tid; idx < 36 * 32; idx += 256) {
    const int r = idx >> 5, w = idx & 31;
    dv[r][w] = hd[r][w] | hd[r + 1][w] | hd[r + 2][w] | hd[r + 3][w] | hd[r + 4][w];
  }
  __syncthreads();

  // phase 4: horizontal erode (1-fill)
  for (int idx = tid; idx < 36 * 32; idx += 256) {
    const int r = idx >> 5, w = idx & 31;
    const unsigned u = dv[r][w];
    const unsigned L = w ? dv[r][w - 1] : 0xFFFFFFFFu;
    const unsigned R = (w < 31) ? dv[r][w + 1] : 0xFFFFFFFFu;
    he[r][w] = u & __funnelshift_r(u, R, 1) & __funnelshift_r(u, R, 2)
                 & __funnelshift_l(L, u, 1) & __funnelshift_l(L, u, 2);
  }
  __syncthreads();

  // phase 5: vertical erode (clipped) + IMAD expand, coalesced uint4 stores
  unsigned* op = (unsigned*)out + ((size_t)ch << 20);
  for (int task = wid; task < 32 * 8; task += 8) {
    const int yy = task >> 3, seg = task & 7;
    const int gy = y0 + yy;
    int lo = gy - 2; if (lo < 0) lo = 0;
    int hi = gy + 2; if (hi > 1023) hi = 1023;
    lo -= (y0 - 2); hi -= (y0 - 2);
    const int word = (seg << 2) + (lane >> 3);
    unsigned o = 0xFFFFFFFFu;
    for (int r = lo; r <= hi; ++r) o &= he[r][word];
    const int sh = (lane & 7) << 2;
    uint4 f;
    f.x = ((o >> (sh    )) & 1u) * 0x3f800000u;
    f.y = ((o >> (sh + 1)) & 1u) * 0x3f800000u;
    f.z = ((o >> (sh + 2)) & 1u) * 0x3f800000u;
    f.w = ((o >> (sh + 3)) & 1u) * 0x3f800000u;
    *(uint4*)(op + ((size_t)gy << 10) + (seg << 7) + (lane << 2)) = f;
  }
}

// ---------------------------------------------------------------------------
extern "C" void kernel_launch(void* const* d_in, const int* in_sizes, int n_in,
                              void* d_out, int out_size) {
  const float* x = (const float*)d_in[0];
  if (n_in > 1 && in_sizes[0] < in_sizes[1]) x = (const float*)d_in[1];

  k_setup   <<<1,    1024>>>();
  k_blur    <<<1024, 256 >>>(x);
  k_flag    <<<1,    64  >>>();
  k_fallback<<<1024, 256 >>>(x);
  k_morph   <<<1024, 256 >>>((float*)d_out);
}